// round 15
// baseline (speedup 1.0000x reference)
#include <cuda_runtime.h>
#include <cuda_fp16.h>
#include <cstdint>
#include <cstddef>

#define Bdim 512
#define Ldim 200
#define Idim 512
#define Hdim 512
#define G3t  1536
#define NCTA 128

// ---------------- device scratch (no runtime allocation) --------------------
__device__ __half g_x16[(size_t)Bdim * Ldim * Idim];     // fp16 x
__device__ __half g_wih16[(size_t)G3t * Idim];           // fp16 w_ih
__device__ __half g_whh16[(size_t)G3t * Hdim];           // fp16 w_hh
// gx in BLOCKED layout: [l][mb(8)][cb(16)][row(64)][gate(3)][col(32)]
__device__ __half g_gx[(size_t)Ldim * Bdim * G3t];
__device__ __half g_h16[2][(size_t)Bdim * Hdim];         // double-buffered fp16 h
__device__ unsigned g_cnt[8];                            // per-mb monotonic barrier
__device__ unsigned g_done[Ldim];                        // per-l gx tile counter

// ---------------- small helpers ---------------------------------------------
static __device__ __forceinline__ unsigned smem_u32(const void* p) {
    return (unsigned)__cvta_generic_to_shared(p);
}
static __device__ __forceinline__ void cp16(unsigned d, const void* s) {
    asm volatile("cp.async.cg.shared.global [%0], [%1], 16;\n" :: "r"(d), "l"(s));
}
static __device__ __forceinline__ void cpcommit() { asm volatile("cp.async.commit_group;\n"); }
static __device__ __forceinline__ void cpwait0()  { asm volatile("cp.async.wait_group 0;\n"); }
static __device__ __forceinline__ void cpwait1()  { asm volatile("cp.async.wait_group 1;\n"); }

#define BAR_SCAN() asm volatile("bar.sync 1, 256;" ::: "memory")
#define BAR_PROD() asm volatile("bar.sync 2, 128;" ::: "memory")

static __device__ __forceinline__ void red_release(unsigned* p, unsigned v) {
    asm volatile("red.release.gpu.global.add.u32 [%0], %1;" :: "l"(p), "r"(v) : "memory");
}
static __device__ __forceinline__ unsigned ld_acquire(const unsigned* p) {
    unsigned v;
    asm volatile("ld.acquire.gpu.global.u32 %0, [%1];" : "=r"(v) : "l"(p) : "memory");
    return v;
}

// ---- bulk async copy + mbarrier --------------------------------------------
static __device__ __forceinline__ void bulk_g2s(unsigned dst, const void* src,
                                                unsigned bytes, unsigned mbar) {
    asm volatile("cp.async.bulk.shared::cluster.global.mbarrier::complete_tx::bytes "
                 "[%0], [%1], %2, [%3];"
                 :: "r"(dst), "l"(src), "r"(bytes), "r"(mbar) : "memory");
}
#define MBAR_INIT(a, c) \
    asm volatile("mbarrier.init.shared.b64 [%0], %1;" :: "r"(a), "r"(c) : "memory")
#define MBAR_EXPECT(a, tx) \
    asm volatile("mbarrier.arrive.expect_tx.shared.b64 _, [%0], %1;" \
                 :: "r"(a), "r"(tx) : "memory")
#define MBAR_WAIT_P(a, par) do {                                                  \
    asm volatile("{\n\t.reg .pred P1;\n\t"                                        \
        "WAIT_LP_%=:\n\t"                                                         \
        "mbarrier.try_wait.parity.acquire.cta.shared::cta.b64 P1, [%0], %1, 0x989680;\n\t" \
        "@P1 bra.uni WAIT_DN_%=;\n\t"                                             \
        "bra.uni WAIT_LP_%=;\n\t"                                                 \
        "WAIT_DN_%=:\n\t}" :: "r"(a), "r"(par) : "memory");                       \
} while (0)

static __device__ __forceinline__ void ldsm4(uint32_t& r0, uint32_t& r1,
                                             uint32_t& r2, uint32_t& r3, unsigned a) {
    asm volatile("ldmatrix.sync.aligned.m8n8.x4.shared.b16 {%0,%1,%2,%3}, [%4];\n"
                 : "=r"(r0), "=r"(r1), "=r"(r2), "=r"(r3) : "r"(a));
}
static __device__ __forceinline__ void mma(float* c, const uint32_t* a,
                                           uint32_t b0, uint32_t b1) {
    asm volatile("mma.sync.aligned.m16n8k16.row.col.f32.f16.f16.f32 "
                 "{%0,%1,%2,%3},{%4,%5,%6,%7},{%8,%9},{%0,%1,%2,%3};\n"
                 : "+f"(c[0]), "+f"(c[1]), "+f"(c[2]), "+f"(c[3])
                 : "r"(a[0]), "r"(a[1]), "r"(a[2]), "r"(a[3]), "r"(b0), "r"(b1));
}
static __device__ __forceinline__ float sigm(float x) { return 1.f / (1.f + __expf(-x)); }
static __device__ __forceinline__ float tanh_f(float x) {
    float e = __expf(2.f * x);
    return 1.f - 2.f / (e + 1.f);   // safe at +/- inf
}

// ---------------- fused prep: 4 fp32->fp16 conversions + flag reset ----------
struct CvtDesc {
    const float* s0; const float* s1; const float* s2; const float* s3;
    __half* d0; __half* d1; __half* d2; __half* d3;
    size_t n0, n1, n2, n3;
};
__global__ __launch_bounds__(256) void k_prep(CvtDesc p) {
    if (blockIdx.x == 0) {
        if (threadIdx.x < 8) g_cnt[threadIdx.x] = 0u;
        for (int i = threadIdx.x; i < Ldim; i += 256) g_done[i] = 0u;
    }
    const float* srcs[4] = {p.s0, p.s1, p.s2, p.s3};
    __half* dsts[4] = {p.d0, p.d1, p.d2, p.d3};
    size_t ns[4] = {p.n0, p.n1, p.n2, p.n3};
    size_t stride = (size_t)gridDim.x * blockDim.x * 4;
    #pragma unroll
    for (int seg = 0; seg < 4; seg++) {
        const float* s = srcs[seg];
        __half* d = dsts[seg];
        size_t n = ns[seg];
        for (size_t i = ((size_t)blockIdx.x * blockDim.x + threadIdx.x) * 4;
             i < n; i += stride) {
            float4 v = *reinterpret_cast<const float4*>(s + i);
            *reinterpret_cast<__half2*>(d + i)     = __floats2half2_rn(v.x, v.y);
            *reinterpret_cast<__half2*>(d + i + 2) = __floats2half2_rn(v.z, v.w);
        }
    }
}

// ---------------- fused kernel: producer (Phase A) + scan --------------------
// 128 CTAs x 384 threads.
//   Warps 0-3  (tid   0..127): gx = x @ w_ih^T producer, 128x64 tiles l-major.
//   Warps 4-11 (tid 128..383): GRU scan, K-split pairs; per-step loads via
//     cp.async.bulk + mbarrier (no per-thread LDGSTS on the scan path).
//
// dynamic smem layout (bytes):
//   [0,      99840)  Ws   96 x 520 halves    (scan W_hh slab)
//   [99840, 166400)  Hs   64 x 520 halves    (scan h slab; bulk rows 1KB)
//   [166400,178688)  sGx  64 x 96 halves     (scan gx[l] block; 1 bulk 12KB)
//   [178688,191488)  sRed 4 x 32 x 25 floats (symmetric hh exchange)
//   [191488,211968)  As   2 x 128 x 40       (producer x tile)
//   [211968,222208)  Bs   2 x 64 x 40        (producer w_ih tile)
//   [222208,222464)  sAtt 64 floats          (att column; 1 bulk 256B)
//   [222464,222472)  mbar
#define SM_TOTAL 222480
#define TILES_PER_L 96      // 4 m-tiles x 24 n-tiles (128x64)
#define TILES_PER_CTA 150   // 19200 / 128

extern __shared__ char s_raw[];
__global__ __launch_bounds__(384) void k_fused(const float* __restrict__ att,
                                               const float* __restrict__ h0,
                                               const float* __restrict__ b_hh,
                                               const float* __restrict__ b_ih,
                                               float* __restrict__ out) {
    const int tid = threadIdx.x;
    const int cta = blockIdx.x;

    if (tid >= 128) {
        // ===================== SCAN half (warps 4-11) ========================
        __half (*Ws)[520] = reinterpret_cast<__half(*)[520]>(s_raw);
        __half (*Hs)[520] = reinterpret_cast<__half(*)[520]>(s_raw + 99840);
        __half (*sGx)[96] = reinterpret_cast<__half(*)[96]>(s_raw + 166400);
        float (*sRed)[32][25] = reinterpret_cast<float(*)[32][25]>(s_raw + 178688);
        float* sAtt = reinterpret_cast<float*>(s_raw + 222208);
        const unsigned mbar = smem_u32(s_raw + 222464);
        const int stid = tid - 128;               // 0..255
        const int lane = stid & 31;
        const int sw = stid >> 5;                 // 0..7
        const int rg = sw & 3;                    // row group (16 rows)
        const int kh = sw >> 2;                   // K-half
        const int cb = cta & 15, mb = cta >> 4;
        const int m0 = mb * 64, j0 = cb * 32;
        const int myr = rg * 16 + (lane >> 2) + kh * 8;   // epilogue row (0..63)

        // load W_hh slab: row n -> gate row g = (n/32)*512 + j0 + (n%32)
        for (int idx = stid; idx < 96 * 64; idx += 256) {
            int n = idx >> 6, seg = idx & 63;
            int g = (n >> 5) * Hdim + j0 + (n & 31);
            *reinterpret_cast<uint4*>(&Ws[n][seg * 8]) =
                *reinterpret_cast<const uint4*>(g_whh16 + (size_t)g * Hdim + seg * 8);
        }
        // hoist b_hh (loop-invariant) into registers
        float bhr[8], bhz[8], bhn[8];
        #pragma unroll
        for (int tn = 0; tn < 4; tn++)
            #pragma unroll
            for (int e = 0; e < 2; e++) {
                int j = j0 + tn * 8 + (lane & 3) * 2 + e;
                bhr[tn * 2 + e] = b_hh[j];
                bhz[tn * 2 + e] = b_hh[Hdim + j];
                bhn[tn * 2 + e] = b_hh[2 * Hdim + j];
            }
        // fp32 carried h: each warp owns its 8 epilogue rows
        float hreg[8];
        #pragma unroll
        for (int tn = 0; tn < 4; tn++)
            #pragma unroll
            for (int e = 0; e < 2; e++) {
                int j = j0 + tn * 8 + (lane & 3) * 2 + e;
                hreg[tn * 2 + e] = h0[(size_t)(m0 + myr) * Hdim + j];
            }
        // mbarrier init + initial gate on gx[0]
        if (stid == 0) {
            MBAR_INIT(mbar, 65);
            while (ld_acquire(&g_done[0]) < (unsigned)TILES_PER_L) {}
        }
        BAR_SCAN();

        float* hx = out + (size_t)Bdim * Ldim * Hdim;

        for (int l = 0; l < Ldim; l++) {
            const __half* hbuf = g_h16[l & 1];
            __half* hnext = g_h16[(l + 1) & 1];

            // ---- issue async bulk loads: 64 h rows + gx block + att ----
            if (stid < 64) {
                MBAR_EXPECT(mbar, 1024u);
                bulk_g2s(smem_u32(&Hs[stid][0]),
                         hbuf + (size_t)(m0 + stid) * Hdim, 1024u, mbar);
            } else if (stid == 64) {
                MBAR_EXPECT(mbar, 12544u);
                bulk_g2s(smem_u32(&sGx[0][0]),
                         g_gx + (((size_t)l * 8 + mb) * 16 + cb) * 6144, 12288u, mbar);
                bulk_g2s(smem_u32(sAtt),
                         att + (size_t)l * Bdim + m0, 256u, mbar);
            }
            MBAR_WAIT_P(mbar, l & 1);

            // ---- K-split MMA: each warp does its 256-wide K half ----
            float acc[12][4];
            #pragma unroll
            for (int i = 0; i < 12; i++)
                #pragma unroll
                for (int k = 0; k < 4; k++) acc[i][k] = 0.f;

            const int kbase = kh * 256;
            for (int kc = kbase; kc < kbase + 256; kc += 64) {
                #pragma unroll
                for (int q = 0; q < 4; q++) {
                    uint32_t a[4], bf[12][2];
                    ldsm4(a[0], a[1], a[2], a[3],
                          smem_u32(&Hs[rg * 16 + (lane & 15)]
                                      [kc + q * 16 + (lane >> 4) * 8]));
                    #pragma unroll
                    for (int bn = 0; bn < 6; bn++) {
                        uint32_t r0, r1, r2, r3;
                        ldsm4(r0, r1, r2, r3,
                              smem_u32(&Ws[bn * 16 + (lane & 15)]
                                          [kc + q * 16 + (lane >> 4) * 8]));
                        bf[bn * 2][0] = r0; bf[bn * 2][1] = r2;
                        bf[bn * 2 + 1][0] = r1; bf[bn * 2 + 1][1] = r3;
                    }
                    #pragma unroll
                    for (int tn = 0; tn < 12; tn++)
                        mma(acc[tn], a, bf[tn][0], bf[tn][1]);
                }
            }

            // ---- symmetric hh exchange (2 barriers) ----
            if (kh) {
                #pragma unroll
                for (int i = 0; i < 12; i++) {
                    sRed[rg][lane][i * 2]     = acc[i][0];
                    sRed[rg][lane][i * 2 + 1] = acc[i][1];
                }
            }
            BAR_SCAN();
            if (!kh) {
                #pragma unroll
                for (int i = 0; i < 12; i++) {
                    acc[i][0] += sRed[rg][lane][i * 2];
                    acc[i][1] += sRed[rg][lane][i * 2 + 1];
                    sRed[rg][lane][i * 2]     = acc[i][2];
                    sRed[rg][lane][i * 2 + 1] = acc[i][3];
                }
            }
            BAR_SCAN();
            if (kh) {
                #pragma unroll
                for (int i = 0; i < 12; i++) {
                    acc[i][2] += sRed[rg][lane][i * 2];
                    acc[i][3] += sRed[rg][lane][i * 2 + 1];
                }
            }

            // ---- gate epilogue: ALL 8 warps, 8 rows each ----
            const int eoff = kh * 2;
            float outv[8];
            {
                int b = m0 + myr;
                float wv = sAtt[myr];
                #pragma unroll
                for (int tn = 0; tn < 4; tn++) {
                    int joff = tn * 8 + (lane & 3) * 2;
                    int j = j0 + joff;
                    __half2 xr2 = *reinterpret_cast<const __half2*>(&sGx[myr][joff]);
                    __half2 xz2 = *reinterpret_cast<const __half2*>(&sGx[myr][32 + joff]);
                    __half2 xn2 = *reinterpret_cast<const __half2*>(&sGx[myr][64 + joff]);
                    __half hv[2];
                    #pragma unroll
                    for (int e = 0; e < 2; e++) {
                        float hr = acc[tn][eoff + e]     + bhr[tn * 2 + e];
                        float hz = acc[tn + 4][eoff + e] + bhz[tn * 2 + e];
                        float hn = acc[tn + 8][eoff + e] + bhn[tn * 2 + e];
                        float xr = e ? __high2float(xr2) : __low2float(xr2);
                        float xz = e ? __high2float(xz2) : __low2float(xz2);
                        float xn = e ? __high2float(xn2) : __low2float(xn2);
                        float rgt = sigm(xr + hr);
                        float zg = sigm(xz + hz);
                        float ng = tanh_f(xn + rgt * hn);
                        float h  = hreg[tn * 2 + e];
                        float ho = (1.f - zg) * ng + zg * h;
                        float hnew = (1.f - wv) * h + wv * ho;
                        hreg[tn * 2 + e] = hnew;
                        outv[tn * 2 + e] = hnew;
                        hv[e] = __float2half_rn(hnew);
                    }
                    *reinterpret_cast<__half2*>(hnext + (size_t)b * Hdim + j) =
                        __halves2half2(hv[0], hv[1]);
                }
            }
            // ---- inter-CTA release/acquire + next-gx gate (merged) ----
            unsigned gen = (unsigned)(l + 1);
            BAR_SCAN();
            if (stid == 0) {
                red_release(&g_cnt[mb], 1u);
                while (ld_acquire(&g_cnt[mb]) < 16u * gen) {}
                if (l + 1 < Ldim) {
                    while (ld_acquire(&g_done[l + 1]) < (unsigned)TILES_PER_L) {}
                }
            }
            BAR_SCAN();
            // deferred dead-weight stores (never read on-device)
            {
                int b = m0 + myr;
                float* orow = out + (size_t)b * Ldim * Hdim + (size_t)l * Hdim;
                #pragma unroll
                for (int tn = 0; tn < 4; tn++) {
                    int j = j0 + tn * 8 + (lane & 3) * 2;
                    float2 v = make_float2(outv[tn * 2], outv[tn * 2 + 1]);
                    *reinterpret_cast<float2*>(orow + j) = v;
                    if (l == Ldim - 1)
                        *reinterpret_cast<float2*>(hx + (size_t)b * Hdim + j) = v;
                }
            }
        }
    } else {
        // ================= PRODUCER half (warps 0-3, 128 thr) ================
        __half (*As)[128][40] = reinterpret_cast<__half(*)[128][40]>(s_raw + 191488);
        __half (*Bs)[64][40] = reinterpret_cast<__half(*)[64][40]>(s_raw + 211968);
        const int ptid = tid;
        const int plane = ptid & 31, pwid = ptid >> 5;

        for (int t = 0; t < TILES_PER_CTA; t++) {
            int T = cta + (t << 7);
            int l = T / TILES_PER_L;
            int r = T - l * TILES_PER_L;
            int mt = r / 24, nt = r - mt * 24;
            int b0 = mt * 128, n0 = nt * 64;

            float acc[2][8][4];
            #pragma unroll
            for (int i = 0; i < 2; i++)
                #pragma unroll
                for (int j = 0; j < 8; j++)
                    #pragma unroll
                    for (int k = 0; k < 4; k++) acc[i][j][k] = 0.f;

            auto loadCk = [&](int st, int kc) {
                #pragma unroll
                for (int i = 0; i < 4; i++) {           // A: 128 rows x 4 segs
                    int idx = i * 128 + ptid;
                    int row = idx >> 2, seg = idx & 3;
                    cp16(smem_u32(&As[st][row][seg * 8]),
                         g_x16 + ((size_t)(b0 + row) * Ldim + l) * Idim + kc + seg * 8);
                }
                #pragma unroll
                for (int i = 0; i < 2; i++) {           // B: 64 rows x 4 segs
                    int idx = i * 128 + ptid;
                    int row = idx >> 2, seg = idx & 3;
                    cp16(smem_u32(&Bs[st][row][seg * 8]),
                         g_wih16 + (size_t)(n0 + row) * Idim + kc + seg * 8);
                }
                cpcommit();
            };
            loadCk(0, 0);
            for (int kc = 0; kc < Idim; kc += 32) {
                int st = (kc >> 5) & 1;
                if (kc + 32 < Idim) { loadCk(st ^ 1, kc + 32); cpwait1(); }
                else cpwait0();
                BAR_PROD();
                #pragma unroll
                for (int q = 0; q < 2; q++) {
                    uint32_t a[2][4], bf[8][2];
                    #pragma unroll
                    for (int tm = 0; tm < 2; tm++)
                        ldsm4(a[tm][0], a[tm][1], a[tm][2], a[tm][3],
                              smem_u32(&As[st][pwid * 32 + tm * 16 + (plane & 15)]
                                              [q * 16 + (plane >> 4) * 8]));
                    #pragma unroll
                    for (int bn = 0; bn < 4; bn++) {
                        uint32_t r0, r1, r2, r3;
                        ldsm4(r0, r1, r2, r3,
                              smem_u32(&Bs[st][bn * 16 + (plane & 15)]
                                              [q * 16 + (plane >> 4) * 8]));
                        bf[bn * 2][0] = r0; bf[bn * 2][1] = r2;
                        bf[bn * 2 + 1][0] = r1; bf[bn * 2 + 1][1] = r3;
                    }
                    #pragma unroll
                    for (int tm = 0; tm < 2; tm++)
                        #pragma unroll
                        for (int tn = 0; tn < 8; tn++)
                            mma(acc[tm][tn], a[tm], bf[tn][0], bf[tn][1]);
                }
                BAR_PROD();
            }
            // epilogue: write blocked gx layout, bias folded
            {
                int gi = n0 >> 9;           // gate index (constant per tile)
                int jb = n0 & 511;          // j base within gate
                #pragma unroll
                for (int tm = 0; tm < 2; tm++)
                    #pragma unroll
                    for (int hh = 0; hh < 2; hh++) {
                        int rr = pwid * 32 + tm * 16 + (plane >> 2) + hh * 8;
                        int b = b0 + rr;
                        int mbp = b >> 6, rowp = b & 63;
                        __half* dstb = g_gx
                            + (((size_t)l * 8 + mbp) * 16) * 6144
                            + (size_t)rowp * 96 + gi * 32;
                        const float* bia = b_ih + n0;
                        #pragma unroll
                        for (int tn = 0; tn < 8; tn++) {
                            int col = tn * 8 + (plane & 3) * 2;
                            int cbp = (jb + col) >> 5;
                            int colp = (jb + col) & 31;
                            *reinterpret_cast<__half2*>(dstb + (size_t)cbp * 6144 + colp) =
                                __floats2half2_rn(acc[tm][tn][hh * 2] + __ldg(bia + col),
                                                  acc[tm][tn][hh * 2 + 1] + __ldg(bia + col + 1));
                        }
                    }
            }
            BAR_PROD();
            if (ptid == 0) red_release(&g_done[l], 1u);
        }
    }
}

// ---------------- launcher ---------------------------------------------------
extern "C" void kernel_launch(void* const* d_in, const int* in_sizes, int n_in,
                              void* d_out, int out_size) {
    const float* x    = (const float*)d_in[0];
    const float* att  = (const float*)d_in[1];
    const float* h0   = (const float*)d_in[2];
    const float* w_ih = (const float*)d_in[3];
    const float* w_hh = (const float*)d_in[4];
    const float* b_ih = (const float*)d_in[5];
    const float* b_hh = (const float*)d_in[6];
    float* out = (float*)d_out;

    void *px, *pwih, *pwhh, *ph;
    cudaGetSymbolAddress(&px, g_x16);
    cudaGetSymbolAddress(&pwih, g_wih16);
    cudaGetSymbolAddress(&pwhh, g_whh16);
    cudaGetSymbolAddress(&ph, g_h16);

    cudaFuncSetAttribute(k_fused, cudaFuncAttributeMaxDynamicSharedMemorySize, SM_TOTAL);

    CvtDesc p;
    p.s0 = x;    p.d0 = (__half*)px;   p.n0 = (size_t)Bdim * Ldim * Idim;
    p.s1 = w_ih; p.d1 = (__half*)pwih; p.n1 = (size_t)G3t * Idim;
    p.s2 = w_hh; p.d2 = (__half*)pwhh; p.n2 = (size_t)G3t * Hdim;
    p.s3 = h0;   p.d3 = (__half*)ph;   p.n3 = (size_t)Bdim * Hdim;
    k_prep<<<4096, 256>>>(p);

    k_fused<<<NCTA, 384, SM_TOTAL>>>(att, h0, b_hh, b_ih, out);
}

// round 16
// speedup vs baseline: 1.0329x; 1.0329x over previous
#include <cuda_runtime.h>
#include <cuda_fp16.h>
#include <cstdint>
#include <cstddef>

#define Bdim 512
#define Ldim 200
#define Idim 512
#define Hdim 512
#define G3t  1536
#define NCTA 128

// ---------------- device scratch (no runtime allocation) --------------------
__device__ __half g_x16[(size_t)Bdim * Ldim * Idim];     // fp16 x
__device__ __half g_wih16[(size_t)G3t * Idim];           // fp16 w_ih
__device__ __half g_whh16[(size_t)G3t * Hdim];           // fp16 w_hh
// gx in BLOCKED layout: [l][mb(8)][cb(16)][row(64)][gate(3)][col(32)]
__device__ __half g_gx[(size_t)Ldim * Bdim * G3t];
__device__ __half g_h16[2][(size_t)Bdim * Hdim];         // double-buffered fp16 h
__device__ unsigned g_cnt2[16 * 32];                     // per-(mb,half) counters, 128B apart
__device__ unsigned g_done[Ldim];                        // per-l gx tile counter

// ---------------- small helpers ---------------------------------------------
static __device__ __forceinline__ unsigned smem_u32(const void* p) {
    return (unsigned)__cvta_generic_to_shared(p);
}
static __device__ __forceinline__ void cp16(unsigned d, const void* s) {
    asm volatile("cp.async.cg.shared.global [%0], [%1], 16;\n" :: "r"(d), "l"(s));
}
static __device__ __forceinline__ void cpcommit() { asm volatile("cp.async.commit_group;\n"); }
static __device__ __forceinline__ void cpwait0()  { asm volatile("cp.async.wait_group 0;\n"); }
static __device__ __forceinline__ void cpwait1()  { asm volatile("cp.async.wait_group 1;\n"); }

#define BAR_SCAN() asm volatile("bar.sync 1, 256;" ::: "memory")
#define BAR_PROD() asm volatile("bar.sync 2, 128;" ::: "memory")
#define BAR_HALF(kh) asm volatile("bar.sync %0, 128;" :: "r"(3 + (kh)) : "memory")

static __device__ __forceinline__ void red_release(unsigned* p, unsigned v) {
    asm volatile("red.release.gpu.global.add.u32 [%0], %1;" :: "l"(p), "r"(v) : "memory");
}
static __device__ __forceinline__ unsigned ld_acquire(const unsigned* p) {
    unsigned v;
    asm volatile("ld.acquire.gpu.global.u32 %0, [%1];" : "=r"(v) : "l"(p) : "memory");
    return v;
}

// ---- bulk async copy + mbarrier --------------------------------------------
static __device__ __forceinline__ void bulk_g2s(unsigned dst, const void* src,
                                                unsigned bytes, unsigned mbar) {
    asm volatile("cp.async.bulk.shared::cluster.global.mbarrier::complete_tx::bytes "
                 "[%0], [%1], %2, [%3];"
                 :: "r"(dst), "l"(src), "r"(bytes), "r"(mbar) : "memory");
}
#define MBAR_INIT(a, c) \
    asm volatile("mbarrier.init.shared.b64 [%0], %1;" :: "r"(a), "r"(c) : "memory")
#define MBAR_EXPECT(a, tx) \
    asm volatile("mbarrier.arrive.expect_tx.shared.b64 _, [%0], %1;" \
                 :: "r"(a), "r"(tx) : "memory")
#define MBAR_WAIT_P(a, par) do {                                                  \
    asm volatile("{\n\t.reg .pred P1;\n\t"                                        \
        "WAIT_LP_%=:\n\t"                                                         \
        "mbarrier.try_wait.parity.acquire.cta.shared::cta.b64 P1, [%0], %1, 0x989680;\n\t" \
        "@P1 bra.uni WAIT_DN_%=;\n\t"                                             \
        "bra.uni WAIT_LP_%=;\n\t"                                                 \
        "WAIT_DN_%=:\n\t}" :: "r"(a), "r"(par) : "memory");                       \
} while (0)

static __device__ __forceinline__ void ldsm4(uint32_t& r0, uint32_t& r1,
                                             uint32_t& r2, uint32_t& r3, unsigned a) {
    asm volatile("ldmatrix.sync.aligned.m8n8.x4.shared.b16 {%0,%1,%2,%3}, [%4];\n"
                 : "=r"(r0), "=r"(r1), "=r"(r2), "=r"(r3) : "r"(a));
}
static __device__ __forceinline__ void mma(float* c, const uint32_t* a,
                                           uint32_t b0, uint32_t b1) {
    asm volatile("mma.sync.aligned.m16n8k16.row.col.f32.f16.f16.f32 "
                 "{%0,%1,%2,%3},{%4,%5,%6,%7},{%8,%9},{%0,%1,%2,%3};\n"
                 : "+f"(c[0]), "+f"(c[1]), "+f"(c[2]), "+f"(c[3])
                 : "r"(a[0]), "r"(a[1]), "r"(a[2]), "r"(a[3]), "r"(b0), "r"(b1));
}
static __device__ __forceinline__ float sigm(float x) { return 1.f / (1.f + __expf(-x)); }
static __device__ __forceinline__ float tanh_f(float x) {
    float e = __expf(2.f * x);
    return 1.f - 2.f / (e + 1.f);   // safe at +/- inf
}

// ---------------- fused prep: 4 fp32->fp16 conversions + flag reset ----------
struct CvtDesc {
    const float* s0; const float* s1; const float* s2; const float* s3;
    __half* d0; __half* d1; __half* d2; __half* d3;
    size_t n0, n1, n2, n3;
};
__global__ __launch_bounds__(256) void k_prep(CvtDesc p) {
    if (blockIdx.x == 0) {
        for (int i = threadIdx.x; i < 16 * 32; i += 256) g_cnt2[i] = 0u;
        for (int i = threadIdx.x; i < Ldim; i += 256) g_done[i] = 0u;
    }
    const float* srcs[4] = {p.s0, p.s1, p.s2, p.s3};
    __half* dsts[4] = {p.d0, p.d1, p.d2, p.d3};
    size_t ns[4] = {p.n0, p.n1, p.n2, p.n3};
    size_t stride = (size_t)gridDim.x * blockDim.x * 4;
    #pragma unroll
    for (int seg = 0; seg < 4; seg++) {
        const float* s = srcs[seg];
        __half* d = dsts[seg];
        size_t n = ns[seg];
        for (size_t i = ((size_t)blockIdx.x * blockDim.x + threadIdx.x) * 4;
             i < n; i += stride) {
            float4 v = *reinterpret_cast<const float4*>(s + i);
            *reinterpret_cast<__half2*>(d + i)     = __floats2half2_rn(v.x, v.y);
            *reinterpret_cast<__half2*>(d + i + 2) = __floats2half2_rn(v.z, v.w);
        }
    }
}

// ---------------- fused kernel: producer (Phase A) + scan --------------------
// 128 CTAs x 384 threads.
//   Warps 0-3  (tid   0..127): gx = x @ w_ih^T producer, 128x64 tiles l-major.
//   Warps 4-11 (tid 128..383): GRU scan, K-split pairs; per-HALF h gating
//     (kh0 waits only on cb0-7's release, kh1 on cb8-15's), bulk loads +
//     3 mbarriers, padded release counters.
//
// dynamic smem layout (bytes):
//   [0,      99840)  Ws   96 x 520 halves    (scan W_hh slab)
//   [99840, 166400)  Hs   64 x 520 halves    (scan h slab; per-half 512B bulks)
//   [166400,178688)  sGx  64 x 96 halves     (scan gx[l] block; 1 bulk 12KB)
//   [178688,191488)  sRed 4 x 32 x 25 floats (symmetric hh exchange)
//   [191488,211968)  As   2 x 128 x 40       (producer x tile)
//   [211968,222208)  Bs   2 x 64 x 40        (producer w_ih tile)
//   [222208,222464)  sAtt 64 floats          (att column; 1 bulk 256B)
//   [222464,222488)  mbar[3]: h-lo, h-hi, gx/att
#define SM_TOTAL 222496
#define TILES_PER_L 96      // 4 m-tiles x 24 n-tiles (128x64)
#define TILES_PER_CTA 150   // 19200 / 128

extern __shared__ char s_raw[];
__global__ __launch_bounds__(384) void k_fused(const float* __restrict__ att,
                                               const float* __restrict__ h0,
                                               const float* __restrict__ b_hh,
                                               const float* __restrict__ b_ih,
                                               float* __restrict__ out) {
    const int tid = threadIdx.x;
    const int cta = blockIdx.x;

    if (tid >= 128) {
        // ===================== SCAN half (warps 4-11) ========================
        __half (*Ws)[520] = reinterpret_cast<__half(*)[520]>(s_raw);
        __half (*Hs)[520] = reinterpret_cast<__half(*)[520]>(s_raw + 99840);
        __half (*sGx)[96] = reinterpret_cast<__half(*)[96]>(s_raw + 166400);
        float (*sRed)[32][25] = reinterpret_cast<float(*)[32][25]>(s_raw + 178688);
        float* sAtt = reinterpret_cast<float*>(s_raw + 222208);
        const unsigned mbarH0 = smem_u32(s_raw + 222464);
        const unsigned mbarH1 = smem_u32(s_raw + 222472);
        const unsigned mbarG  = smem_u32(s_raw + 222480);
        const int stid = tid - 128;               // 0..255
        const int lane = stid & 31;
        const int sw = stid >> 5;                 // 0..7
        const int rg = sw & 3;                    // row group (16 rows)
        const int kh = sw >> 2;                   // K-half (stid<128 -> 0)
        const int hs = stid & 127;                // index within half-subgroup
        const int cb = cta & 15, mb = cta >> 4;
        const int m0 = mb * 64, j0 = cb * 32;
        const int myr = rg * 16 + (lane >> 2) + kh * 8;   // epilogue row (0..63)
        const unsigned mbarMine = kh ? mbarH1 : mbarH0;
        unsigned* myCnt  = &g_cnt2[(mb * 2 + kh) * 32];          // counter I consume
        unsigned* relCnt = &g_cnt2[(mb * 2 + (cb >> 3)) * 32];   // counter I release

        // load W_hh slab: row n -> gate row g = (n/32)*512 + j0 + (n%32)
        for (int idx = stid; idx < 96 * 64; idx += 256) {
            int n = idx >> 6, seg = idx & 63;
            int g = (n >> 5) * Hdim + j0 + (n & 31);
            *reinterpret_cast<uint4*>(&Ws[n][seg * 8]) =
                *reinterpret_cast<const uint4*>(g_whh16 + (size_t)g * Hdim + seg * 8);
        }
        // hoist b_hh (loop-invariant) into registers
        float bhr[8], bhz[8], bhn[8];
        #pragma unroll
        for (int tn = 0; tn < 4; tn++)
            #pragma unroll
            for (int e = 0; e < 2; e++) {
                int j = j0 + tn * 8 + (lane & 3) * 2 + e;
                bhr[tn * 2 + e] = b_hh[j];
                bhz[tn * 2 + e] = b_hh[Hdim + j];
                bhn[tn * 2 + e] = b_hh[2 * Hdim + j];
            }
        // fp32 carried h: each warp owns its 8 epilogue rows
        float hreg[8];
        #pragma unroll
        for (int tn = 0; tn < 4; tn++)
            #pragma unroll
            for (int e = 0; e < 2; e++) {
                int j = j0 + tn * 8 + (lane & 3) * 2 + e;
                hreg[tn * 2 + e] = h0[(size_t)(m0 + myr) * Hdim + j];
            }
        // mbarrier init + initial gate on gx[0]
        if (stid == 0) {
            MBAR_INIT(mbarH0, 1);
            MBAR_INIT(mbarH1, 1);
            MBAR_INIT(mbarG, 1);
            while (ld_acquire(&g_done[0]) < (unsigned)TILES_PER_L) {}
        }
        BAR_SCAN();

        float* hx = out + (size_t)Bdim * Ldim * Hdim;

        for (int l = 0; l < Ldim; l++) {
            const __half* hbuf = g_h16[l & 1];
            __half* hnext = g_h16[(l + 1) & 1];

            // ---- per-half gate on previous step's producers + bulk h load ----
            if (hs == 0) {
                if (l) {
                    unsigned need = 8u * (unsigned)l;
                    while (ld_acquire(myCnt) < need) {}
                }
                MBAR_EXPECT(mbarMine, 32768u);
            }
            BAR_HALF(kh);
            if (hs < 64) {
                bulk_g2s(smem_u32(&Hs[hs][0]) + kh * 512u,
                         hbuf + (size_t)(m0 + hs) * Hdim + kh * 256, 512u, mbarMine);
            }
            // gx + att (gated by g_done merged at bottom; issued by one thread)
            if (stid == 0) {
                MBAR_EXPECT(mbarG, 12544u);
                bulk_g2s(smem_u32(&sGx[0][0]),
                         g_gx + (((size_t)l * 8 + mb) * 16 + cb) * 6144, 12288u, mbarG);
                bulk_g2s(smem_u32(sAtt),
                         att + (size_t)l * Bdim + m0, 256u, mbarG);
            }
            MBAR_WAIT_P(mbarMine, l & 1);

            // ---- K-split MMA: each warp does its 256-wide K half ----
            float acc[12][4];
            #pragma unroll
            for (int i = 0; i < 12; i++)
                #pragma unroll
                for (int k = 0; k < 4; k++) acc[i][k] = 0.f;

            const int kbase = kh * 256;
            for (int kc = kbase; kc < kbase + 256; kc += 64) {
                #pragma unroll
                for (int q = 0; q < 4; q++) {
                    uint32_t a[4], bf[12][2];
                    ldsm4(a[0], a[1], a[2], a[3],
                          smem_u32(&Hs[rg * 16 + (lane & 15)]
                                      [kc + q * 16 + (lane >> 4) * 8]));
                    #pragma unroll
                    for (int bn = 0; bn < 6; bn++) {
                        uint32_t r0, r1, r2, r3;
                        ldsm4(r0, r1, r2, r3,
                              smem_u32(&Ws[bn * 16 + (lane & 15)]
                                          [kc + q * 16 + (lane >> 4) * 8]));
                        bf[bn * 2][0] = r0; bf[bn * 2][1] = r2;
                        bf[bn * 2 + 1][0] = r1; bf[bn * 2 + 1][1] = r3;
                    }
                    #pragma unroll
                    for (int tn = 0; tn < 12; tn++)
                        mma(acc[tn], a, bf[tn][0], bf[tn][1]);
                }
            }

            // ---- symmetric hh exchange (2 barriers) ----
            if (kh) {
                #pragma unroll
                for (int i = 0; i < 12; i++) {
                    sRed[rg][lane][i * 2]     = acc[i][0];
                    sRed[rg][lane][i * 2 + 1] = acc[i][1];
                }
            }
            BAR_SCAN();
            if (!kh) {
                #pragma unroll
                for (int i = 0; i < 12; i++) {
                    acc[i][0] += sRed[rg][lane][i * 2];
                    acc[i][1] += sRed[rg][lane][i * 2 + 1];
                    sRed[rg][lane][i * 2]     = acc[i][2];
                    sRed[rg][lane][i * 2 + 1] = acc[i][3];
                }
            }
            BAR_SCAN();
            if (kh) {
                #pragma unroll
                for (int i = 0; i < 12; i++) {
                    acc[i][2] += sRed[rg][lane][i * 2];
                    acc[i][3] += sRed[rg][lane][i * 2 + 1];
                }
            }
            // gx/att must be resident before epilogue reads
            MBAR_WAIT_P(mbarG, l & 1);

            // ---- gate epilogue: ALL 8 warps, 8 rows each ----
            const int eoff = kh * 2;
            float outv[8];
            {
                int b = m0 + myr;
                float wv = sAtt[myr];
                #pragma unroll
                for (int tn = 0; tn < 4; tn++) {
                    int joff = tn * 8 + (lane & 3) * 2;
                    int j = j0 + joff;
                    __half2 xr2 = *reinterpret_cast<const __half2*>(&sGx[myr][joff]);
                    __half2 xz2 = *reinterpret_cast<const __half2*>(&sGx[myr][32 + joff]);
                    __half2 xn2 = *reinterpret_cast<const __half2*>(&sGx[myr][64 + joff]);
                    __half hv[2];
                    #pragma unroll
                    for (int e = 0; e < 2; e++) {
                        float hr = acc[tn][eoff + e]     + bhr[tn * 2 + e];
                        float hz = acc[tn + 4][eoff + e] + bhz[tn * 2 + e];
                        float hn = acc[tn + 8][eoff + e] + bhn[tn * 2 + e];
                        float xr = e ? __high2float(xr2) : __low2float(xr2);
                        float xz = e ? __high2float(xz2) : __low2float(xz2);
                        float xn = e ? __high2float(xn2) : __low2float(xn2);
                        float rgt = sigm(xr + hr);
                        float zg = sigm(xz + hz);
                        float ng = tanh_f(xn + rgt * hn);
                        float h  = hreg[tn * 2 + e];
                        float ho = (1.f - zg) * ng + zg * h;
                        float hnew = (1.f - wv) * h + wv * ho;
                        hreg[tn * 2 + e] = hnew;
                        outv[tn * 2 + e] = hnew;
                        hv[e] = __float2half_rn(hnew);
                    }
                    *reinterpret_cast<__half2*>(hnext + (size_t)b * Hdim + j) =
                        __halves2half2(hv[0], hv[1]);
                }
            }
            // ---- release (wait moved to next step's top) + next-gx gate ----
            BAR_SCAN();
            if (stid == 0) {
                red_release(relCnt, 1u);
                if (l + 1 < Ldim) {
                    while (ld_acquire(&g_done[l + 1]) < (unsigned)TILES_PER_L) {}
                }
            }
            // deferred dead-weight stores (never read on-device)
            {
                int b = m0 + myr;
                float* orow = out + (size_t)b * Ldim * Hdim + (size_t)l * Hdim;
                #pragma unroll
                for (int tn = 0; tn < 4; tn++) {
                    int j = j0 + tn * 8 + (lane & 3) * 2;
                    float2 v = make_float2(outv[tn * 2], outv[tn * 2 + 1]);
                    *reinterpret_cast<float2*>(orow + j) = v;
                    if (l == Ldim - 1)
                        *reinterpret_cast<float2*>(hx + (size_t)b * Hdim + j) = v;
                }
            }
        }
    } else {
        // ================= PRODUCER half (warps 0-3, 128 thr) ================
        __half (*As)[128][40] = reinterpret_cast<__half(*)[128][40]>(s_raw + 191488);
        __half (*Bs)[64][40] = reinterpret_cast<__half(*)[64][40]>(s_raw + 211968);
        const int ptid = tid;
        const int plane = ptid & 31, pwid = ptid >> 5;

        for (int t = 0; t < TILES_PER_CTA; t++) {
            int T = cta + (t << 7);
            int l = T / TILES_PER_L;
            int r = T - l * TILES_PER_L;
            int mt = r / 24, nt = r - mt * 24;
            int b0 = mt * 128, n0 = nt * 64;

            float acc[2][8][4];
            #pragma unroll
            for (int i = 0; i < 2; i++)
                #pragma unroll
                for (int j = 0; j < 8; j++)
                    #pragma unroll
                    for (int k = 0; k < 4; k++) acc[i][j][k] = 0.f;

            auto loadCk = [&](int st, int kc) {
                #pragma unroll
                for (int i = 0; i < 4; i++) {           // A: 128 rows x 4 segs
                    int idx = i * 128 + ptid;
                    int row = idx >> 2, seg = idx & 3;
                    cp16(smem_u32(&As[st][row][seg * 8]),
                         g_x16 + ((size_t)(b0 + row) * Ldim + l) * Idim + kc + seg * 8);
                }
                #pragma unroll
                for (int i = 0; i < 2; i++) {           // B: 64 rows x 4 segs
                    int idx = i * 128 + ptid;
                    int row = idx >> 2, seg = idx & 3;
                    cp16(smem_u32(&Bs[st][row][seg * 8]),
                         g_wih16 + (size_t)(n0 + row) * Idim + kc + seg * 8);
                }
                cpcommit();
            };
            loadCk(0, 0);
            for (int kc = 0; kc < Idim; kc += 32) {
                int st = (kc >> 5) & 1;
                if (kc + 32 < Idim) { loadCk(st ^ 1, kc + 32); cpwait1(); }
                else cpwait0();
                BAR_PROD();
                #pragma unroll
                for (int q = 0; q < 2; q++) {
                    uint32_t a[2][4], bf[8][2];
                    #pragma unroll
                    for (int tm = 0; tm < 2; tm++)
                        ldsm4(a[tm][0], a[tm][1], a[tm][2], a[tm][3],
                              smem_u32(&As[st][pwid * 32 + tm * 16 + (plane & 15)]
                                              [q * 16 + (plane >> 4) * 8]));
                    #pragma unroll
                    for (int bn = 0; bn < 4; bn++) {
                        uint32_t r0, r1, r2, r3;
                        ldsm4(r0, r1, r2, r3,
                              smem_u32(&Bs[st][bn * 16 + (plane & 15)]
                                              [q * 16 + (plane >> 4) * 8]));
                        bf[bn * 2][0] = r0; bf[bn * 2][1] = r2;
                        bf[bn * 2 + 1][0] = r1; bf[bn * 2 + 1][1] = r3;
                    }
                    #pragma unroll
                    for (int tm = 0; tm < 2; tm++)
                        #pragma unroll
                        for (int tn = 0; tn < 8; tn++)
                            mma(acc[tm][tn], a[tm], bf[tn][0], bf[tn][1]);
                }
                BAR_PROD();
            }
            // epilogue: write blocked gx layout, bias folded
            {
                int gi = n0 >> 9;           // gate index (constant per tile)
                int jb = n0 & 511;          // j base within gate
                #pragma unroll
                for (int tm = 0; tm < 2; tm++)
                    #pragma unroll
                    for (int hh = 0; hh < 2; hh++) {
                        int rr = pwid * 32 + tm * 16 + (plane >> 2) + hh * 8;
                        int b = b0 + rr;
                        int mbp = b >> 6, rowp = b & 63;
                        __half* dstb = g_gx
                            + (((size_t)l * 8 + mbp) * 16) * 6144
                            + (size_t)rowp * 96 + gi * 32;
                        const float* bia = b_ih + n0;
                        #pragma unroll
                        for (int tn = 0; tn < 8; tn++) {
                            int col = tn * 8 + (plane & 3) * 2;
                            int cbp = (jb + col) >> 5;
                            int colp = (jb + col) & 31;
                            *reinterpret_cast<__half2*>(dstb + (size_t)cbp * 6144 + colp) =
                                __floats2half2_rn(acc[tm][tn][hh * 2] + __ldg(bia + col),
                                                  acc[tm][tn][hh * 2 + 1] + __ldg(bia + col + 1));
                        }
                    }
            }
            BAR_PROD();
            if (ptid == 0) red_release(&g_done[l], 1u);
        }
    }
}

// ---------------- launcher ---------------------------------------------------
extern "C" void kernel_launch(void* const* d_in, const int* in_sizes, int n_in,
                              void* d_out, int out_size) {
    const float* x    = (const float*)d_in[0];
    const float* att  = (const float*)d_in[1];
    const float* h0   = (const float*)d_in[2];
    const float* w_ih = (const float*)d_in[3];
    const float* w_hh = (const float*)d_in[4];
    const float* b_ih = (const float*)d_in[5];
    const float* b_hh = (const float*)d_in[6];
    float* out = (float*)d_out;

    void *px, *pwih, *pwhh, *ph;
    cudaGetSymbolAddress(&px, g_x16);
    cudaGetSymbolAddress(&pwih, g_wih16);
    cudaGetSymbolAddress(&pwhh, g_whh16);
    cudaGetSymbolAddress(&ph, g_h16);

    cudaFuncSetAttribute(k_fused, cudaFuncAttributeMaxDynamicSharedMemorySize, SM_TOTAL);

    CvtDesc p;
    p.s0 = x;    p.d0 = (__half*)px;   p.n0 = (size_t)Bdim * Ldim * Idim;
    p.s1 = w_ih; p.d1 = (__half*)pwih; p.n1 = (size_t)G3t * Idim;
    p.s2 = w_hh; p.d2 = (__half*)pwhh; p.n2 = (size_t)G3t * Hdim;
    p.s3 = h0;   p.d3 = (__half*)ph;   p.n3 = (size_t)Bdim * Hdim;
    k_prep<<<4096, 256>>>(p);

    k_fused<<<NCTA, 384, SM_TOTAL>>>(att, h0, b_hh, b_ih, out);
}